// round 10
// baseline (speedup 1.0000x reference)
#include <cuda_runtime.h>
#include <cuda_fp16.h>
#include <cstdint>
#include <math.h>

// ---------------------------------------------------------------------------
// GraphSAGE fraud detector — round 9.
//  * FIX: CSR scan was a 108us single-block serial kernel (ncu round-8).
//    Replaced with tiled warp-shuffle block scan (~10us).
//  * All-fp16 mma.sync GEMMs, CTA 128x256, warp 64x64, 4-stage cp.async.
//  * CSR-gather aggregation; head fused into GEMM2 epilogue.
// ---------------------------------------------------------------------------

#define MAXN 50048
#define MAXE 409600
#define HDIM 512
#define FDIM 128

#define STAGES   4
#define ASTAGE   8192     // 128 rows x 32 fp16
#define BSTAGE   16384    // 256 rows x 32 fp16
#define SMEM_TOT (STAGES * (ASTAGE + BSTAGE))   // 98304

__device__ __align__(16) float  g_inv[MAXN];
__device__ __align__(16) __half g_xh [(size_t)MAXN * FDIM];
__device__ __align__(16) __half g_ag1[(size_t)MAXN * FDIM];
__device__ __align__(16) __half g_h1 [(size_t)MAXN * HDIM];
__device__ __align__(16) __half g_ag2[(size_t)MAXN * HDIM];
__device__ __align__(16) __half g_w1h[(size_t)HDIM * 256];
__device__ __align__(16) __half g_w2h[(size_t)HDIM * 1024];
__device__ int g_cnt[MAXN];
__device__ int g_off[MAXN + 1];
__device__ int g_eid[MAXE];

// ======================= helpers =============================

__device__ __forceinline__ uint32_t smem_u32(const void* p) {
    uint32_t a;
    asm("{ .reg .u64 t; cvta.to.shared.u64 t, %1; cvt.u32.u64 %0, t; }"
        : "=r"(a) : "l"(p));
    return a;
}

__device__ __forceinline__ void ldsm4(uint32_t* r, uint32_t addr) {
    asm volatile("ldmatrix.sync.aligned.m8n8.x4.shared.b16 {%0,%1,%2,%3}, [%4];"
                 : "=r"(r[0]), "=r"(r[1]), "=r"(r[2]), "=r"(r[3]) : "r"(addr));
}

__device__ __forceinline__ void mma16816(float* d, const uint32_t* a, const uint32_t* b) {
    asm volatile(
        "mma.sync.aligned.m16n8k16.row.col.f32.f16.f16.f32 "
        "{%0,%1,%2,%3}, {%4,%5,%6,%7}, {%8,%9}, {%0,%1,%2,%3};"
        : "+f"(d[0]), "+f"(d[1]), "+f"(d[2]), "+f"(d[3])
        : "r"(a[0]), "r"(a[1]), "r"(a[2]), "r"(a[3]), "r"(b[0]), "r"(b[1]));
}

__device__ __forceinline__ void cp16(uint32_t dst, const void* src, int src_sz) {
    asm volatile("cp.async.cg.shared.global [%0], [%1], 16, %2;"
                 :: "r"(dst), "l"(src), "r"(src_sz) : "memory");
}

#define CP_COMMIT() asm volatile("cp.async.commit_group;" ::: "memory")
#define CP_WAIT2()  asm volatile("cp.async.wait_group 2;" ::: "memory")

__device__ __forceinline__ uint32_t pack_h2(float a, float b) {
    __half2 h = __floats2half2_rn(a, b);
    return *(uint32_t*)&h;
}

// 2 logical rows per 128B physical row, XOR swizzle over 8 16B slots.
__device__ __forceinline__ uint32_t taddr(int r, int c16) {
    return (uint32_t)((r >> 1) * 128 + ((((r & 1) * 4 + c16) ^ ((r >> 1) & 7)) << 4));
}

// ======================= CSR build =============================

__global__ void zeroi_kernel(int* __restrict__ p, int n) {
    int i = blockIdx.x * blockDim.x + threadIdx.x;
    if (i < n) p[i] = 0;
}

__global__ void count_kernel(const int* __restrict__ dst, int E, int* __restrict__ cnt) {
    int e = blockIdx.x * blockDim.x + threadIdx.x;
    if (e < E) atomicAdd(&cnt[dst[e]], 1);
}

// Tiled block-scan (1 block, 1024 threads): exclusive scan of cnt -> off,
// inv[i] = 1/max(cnt,1), cnt cleared for fill's position counters.
// Per 1024-tile: warp shfl inclusive scan + 2-level combine (4 barriers).
__global__ void scan_kernel(int* __restrict__ cnt, int* __restrict__ off,
                            float* __restrict__ inv, int n) {
    __shared__ int wsum[32];
    __shared__ int carry;
    const int t    = threadIdx.x;
    const int lane = t & 31;
    const int wid  = t >> 5;
    if (t == 0) carry = 0;
    __syncthreads();

    for (int base = 0; base < n; base += 1024) {
        const int i = base + t;
        int c = 0;
        if (i < n) {
            c = cnt[i];
            cnt[i] = 0;
            inv[i] = 1.0f / fmaxf((float)c, 1.0f);
        }
        // warp inclusive scan
        int v = c;
#pragma unroll
        for (int o = 1; o < 32; o <<= 1) {
            int u = __shfl_up_sync(0xffffffffu, v, o);
            if (lane >= o) v += u;
        }
        if (lane == 31) wsum[wid] = v;
        __syncthreads();
        if (wid == 0) {
            int w = wsum[lane];
#pragma unroll
            for (int o = 1; o < 32; o <<= 1) {
                int u = __shfl_up_sync(0xffffffffu, w, o);
                if (lane >= o) w += u;
            }
            wsum[lane] = w;
        }
        __syncthreads();
        const int wexcl = (wid == 0) ? 0 : wsum[wid - 1];
        if (i < n) off[i] = carry + wexcl + v - c;
        __syncthreads();               // everyone done reading carry
        if (t == 0) carry += wsum[31]; // tile total
        __syncthreads();
    }
    if (t == 0) off[n] = carry;
}

__global__ void fill_kernel(const int* __restrict__ src, const int* __restrict__ dst,
                            int E, const int* __restrict__ off,
                            int* __restrict__ pos, int* __restrict__ eid) {
    int e = blockIdx.x * blockDim.x + threadIdx.x;
    if (e < E) {
        int d = dst[e];
        int p = atomicAdd(&pos[d], 1);
        eid[off[d] + p] = src[e];
    }
}

// ---------------- fused fp32 -> fp16 convert: x, W1, W2 --------------------
__global__ void tohalf_all(const float* __restrict__ x,  __half* __restrict__ xh,  int nx4,
                           const float* __restrict__ w1, __half* __restrict__ w1h, int nw14,
                           const float* __restrict__ w2, __half* __restrict__ w2h, int nw24) {
    int i = blockIdx.x * blockDim.x + threadIdx.x;
    const float* sp; __half* dp;
    if (i < nx4)                { sp = x;  dp = xh; }
    else if (i < nx4 + nw14)    { sp = w1; dp = w1h; i -= nx4; }
    else if (i < nx4 + nw14 + nw24) { sp = w2; dp = w2h; i -= nx4 + nw14; }
    else return;
    float4 v = ((const float4*)sp)[i];
    uint2 o;
    o.x = pack_h2(v.x, v.y);
    o.y = pack_h2(v.z, v.w);
    ((uint2*)dp)[i] = o;
}

// ---------------- CSR gather (fp16): mean of incoming features -------------
template <int U>
__global__ void gather_f16(const __half* __restrict__ feat,
                           const int* __restrict__ off,
                           const int* __restrict__ eid,
                           const float* __restrict__ inv,
                           __half* __restrict__ outp, int N,
                           const float* __restrict__ bo, float* __restrict__ outInit) {
    const int g = blockIdx.x * (256 / U) + threadIdx.x / U;
    const int c = threadIdx.x % U;
    if (g >= N) return;
    if (bo != nullptr && c == 0) outInit[g] = bo[0];
    const int b  = off[g];
    const int e2 = off[g + 1];
    float acc[8];
#pragma unroll
    for (int q = 0; q < 8; ++q) acc[q] = 0.f;
    const uint4* base = (const uint4*)feat;
#pragma unroll 4
    for (int j = b; j < e2; ++j) {
        int s = __ldg(&eid[j]);
        uint4 u = __ldg(&base[(long long)s * U + c]);
        const __half2* h = (const __half2*)&u;
#pragma unroll
        for (int q = 0; q < 4; ++q) {
            float2 f = __half22float2(h[q]);
            acc[2 * q]     += f.x;
            acc[2 * q + 1] += f.y;
        }
    }
    const float sc = inv[g];
    uint4 o;
    o.x = pack_h2(acc[0] * sc, acc[1] * sc);
    o.y = pack_h2(acc[2] * sc, acc[3] * sc);
    o.z = pack_h2(acc[4] * sc, acc[5] * sc);
    o.w = pack_h2(acc[6] * sc, acc[7] * sc);
    ((uint4*)outp)[(long long)g * U + c] = o;
}

// =================== mma.sync fp16 concat-GEMM, 4-stage ====================
// CTA 128(M) x 256(N); 8 warps, each 64x64; K chunks of 32.
// FUSED 0: epilogue bias+ReLU -> fp16 C.
// FUSED 1: epilogue head: atomicAdd(outLogit[m], sum_n relu(.)*Wo[n]).

template <int FUSED>
__global__ void __launch_bounds__(256, 1)
gemm_f16(const __half* __restrict__ A1, const __half* __restrict__ A2,
         const __half* __restrict__ W,
         const float* __restrict__ bias, __half* __restrict__ C,
         const float* __restrict__ Wo, float* __restrict__ outLogit,
         int M, int Kh) {
    extern __shared__ __align__(128) uint8_t dynsmem[];
    const uint32_t sbA = smem_u32(dynsmem);
    const uint32_t sbB = sbA + STAGES * ASTAGE;

    const int tid  = threadIdx.x;
    const int wid  = tid >> 5;
    const int lane = tid & 31;
    const int wm   = wid & 1;
    const int wn   = wid >> 1;
    const int K    = 2 * Kh;
    const int m0   = blockIdx.x * 128;
    const int n0   = blockIdx.y * 256;

    const int qrow = lane & 15;
    const int qsel = lane >> 4;

    float acc[4][8][4];
#pragma unroll
    for (int i = 0; i < 4; ++i)
#pragma unroll
        for (int j = 0; j < 8; ++j)
#pragma unroll
            for (int r = 0; r < 4; ++r) acc[i][j][r] = 0.0f;

    const int nch = K >> 5;

    auto issue_chunk = [&](int ch, int st) {
        const int k0 = ch << 5;
        const bool useA2 = (k0 >= Kh);
        const int koff = useA2 ? k0 - Kh : k0;
        const __half* Ab = useA2 ? A2 : A1;
        const uint32_t abase = sbA + st * ASTAGE;
        const uint32_t bbase = sbB + st * BSTAGE;
#pragma unroll
        for (int u0 = 0; u0 < 2; ++u0) {
            const int u = tid + u0 * 256;
            const int row = u >> 2, c16 = u & 3;
            const int m = m0 + row;
            const void* src = Ab + (long long)m * Kh + koff + c16 * 8;
            cp16(abase + taddr(row, c16), src, (m < M) ? 16 : 0);
        }
#pragma unroll
        for (int u0 = 0; u0 < 4; ++u0) {
            const int u = tid + u0 * 256;
            const int row = u >> 2, c16 = u & 3;
            const void* src = W + (long long)(n0 + row) * K + k0 + c16 * 8;
            cp16(bbase + taddr(row, c16), src, 16);
        }
    };

    issue_chunk(0, 0); CP_COMMIT();
    issue_chunk(1, 1); CP_COMMIT();
    issue_chunk(2, 2); CP_COMMIT();

    for (int ch = 0; ch < nch; ++ch) {
        CP_WAIT2();
        __syncthreads();
        {
            const int nxt = ch + STAGES - 1;
            if (nxt < nch) issue_chunk(nxt, nxt % STAGES);
            CP_COMMIT();
        }

        const int st = ch % STAGES;
        const uint32_t aST = sbA + st * ASTAGE;
        const uint32_t bST = sbB + st * BSTAGE;

#pragma unroll
        for (int s = 0; s < 2; ++s) {
            const int cc = s * 2 + qsel;
            uint32_t ah[4][4], bh[4][4];
#pragma unroll
            for (int i = 0; i < 4; ++i)
                ldsm4(ah[i], aST + taddr(wm * 64 + i * 16 + qrow, cc));
#pragma unroll
            for (int p = 0; p < 4; ++p)
                ldsm4(bh[p], bST + taddr(wn * 64 + p * 16 + qrow, cc));
#pragma unroll
            for (int i = 0; i < 4; ++i) {
#pragma unroll
                for (int p = 0; p < 4; ++p) {
                    uint32_t f0[2] = { bh[p][0], bh[p][2] };
                    uint32_t f1[2] = { bh[p][1], bh[p][3] };
                    mma16816(acc[i][2 * p],     ah[i], f0);
                    mma16816(acc[i][2 * p + 1], ah[i], f1);
                }
            }
        }
    }
    __syncthreads();

    if (FUSED == 0) {
#pragma unroll
        for (int j = 0; j < 8; ++j) {
            const int nb = n0 + wn * 64 + j * 8 + (lane & 3) * 2;
            const float b0f = bias[nb], b1f = bias[nb + 1];
#pragma unroll
            for (int i = 0; i < 4; ++i) {
                const int r0 = m0 + wm * 64 + i * 16 + (lane >> 2);
                if (r0 < M) {
                    *(uint32_t*)(C + (long long)r0 * HDIM + nb) =
                        pack_h2(fmaxf(acc[i][j][0] + b0f, 0.f),
                                fmaxf(acc[i][j][1] + b1f, 0.f));
                }
                const int r1 = r0 + 8;
                if (r1 < M) {
                    *(uint32_t*)(C + (long long)r1 * HDIM + nb) =
                        pack_h2(fmaxf(acc[i][j][2] + b0f, 0.f),
                                fmaxf(acc[i][j][3] + b1f, 0.f));
                }
            }
        }
    } else {
#pragma unroll
        for (int i = 0; i < 4; ++i) {
            float p0 = 0.f, p1 = 0.f;
#pragma unroll
            for (int j = 0; j < 8; ++j) {
                const int nb = n0 + wn * 64 + j * 8 + (lane & 3) * 2;
                const float b0f = bias[nb],  b1f = bias[nb + 1];
                const float w0 = __ldg(&Wo[nb]), w1 = __ldg(&Wo[nb + 1]);
                p0 += fmaxf(acc[i][j][0] + b0f, 0.f) * w0
                    + fmaxf(acc[i][j][1] + b1f, 0.f) * w1;
                p1 += fmaxf(acc[i][j][2] + b0f, 0.f) * w0
                    + fmaxf(acc[i][j][3] + b1f, 0.f) * w1;
            }
            p0 += __shfl_xor_sync(0xffffffffu, p0, 1);
            p0 += __shfl_xor_sync(0xffffffffu, p0, 2);
            p1 += __shfl_xor_sync(0xffffffffu, p1, 1);
            p1 += __shfl_xor_sync(0xffffffffu, p1, 2);
            if ((lane & 3) == 0) {
                const int r0 = m0 + wm * 64 + i * 16 + (lane >> 2);
                const int r1 = r0 + 8;
                if (r0 < M) atomicAdd(&outLogit[r0], p0);
                if (r1 < M) atomicAdd(&outLogit[r1], p1);
            }
        }
    }
}

// ---------------- sigmoid ----------------
__global__ void sigmoid_kernel(float* __restrict__ out, int n) {
    int i = blockIdx.x * blockDim.x + threadIdx.x;
    if (i < n) out[i] = 1.0f / (1.0f + expf(-out[i]));
}

// ---------------- launch ----------------

extern "C" void kernel_launch(void* const* d_in, const int* in_sizes, int n_in,
                              void* d_out, int out_size) {
    const float* x  = (const float*)d_in[0];
    const int*   ei = (const int*)  d_in[1];
    const float* W1 = (const float*)d_in[2];
    const float* b1 = (const float*)d_in[3];
    const float* W2 = (const float*)d_in[4];
    const float* b2 = (const float*)d_in[5];
    const float* Wo = (const float*)d_in[6];
    const float* bo = (const float*)d_in[7];
    float* out = (float*)d_out;

    const int N = in_sizes[0] / FDIM;
    const int E = in_sizes[1] / 2;
    const int* src = ei;
    const int* dst = ei + E;

    float *inv;
    __half *xh, *ag1, *h1, *ag2, *w1h, *w2h;
    int *cnt, *off, *eid;
    cudaGetSymbolAddress((void**)&inv, g_inv);
    cudaGetSymbolAddress((void**)&xh,  g_xh);
    cudaGetSymbolAddress((void**)&ag1, g_ag1);
    cudaGetSymbolAddress((void**)&h1,  g_h1);
    cudaGetSymbolAddress((void**)&ag2, g_ag2);
    cudaGetSymbolAddress((void**)&w1h, g_w1h);
    cudaGetSymbolAddress((void**)&w2h, g_w2h);
    cudaGetSymbolAddress((void**)&cnt, g_cnt);
    cudaGetSymbolAddress((void**)&off, g_off);
    cudaGetSymbolAddress((void**)&eid, g_eid);

    cudaFuncSetAttribute(gemm_f16<0>, cudaFuncAttributeMaxDynamicSharedMemorySize, SMEM_TOT);
    cudaFuncSetAttribute(gemm_f16<1>, cudaFuncAttributeMaxDynamicSharedMemorySize, SMEM_TOT);

    const int T = 256;

    // ---- converts (no CSR dependency) ----
    const int nx4  = N * FDIM / 4;
    const int nw14 = HDIM * 2 * FDIM / 4;
    const int nw24 = HDIM * 2 * HDIM / 4;
    const int tot4 = nx4 + nw14 + nw24;
    tohalf_all<<<(tot4 + T - 1) / T, T>>>(x, xh, nx4, W1, w1h, nw14, W2, w2h, nw24);

    // ---- CSR build ----
    zeroi_kernel<<<(N + T - 1) / T, T>>>(cnt, N);
    count_kernel<<<(E + T - 1) / T, T>>>(dst, E, cnt);
    scan_kernel<<<1, 1024>>>(cnt, off, inv, N);
    fill_kernel<<<(E + T - 1) / T, T>>>(src, dst, E, off, cnt, eid);

    // ---- layer 1 ----
    gather_f16<16><<<(N + 15) / 16, 256>>>(xh, off, eid, inv, ag1, N, nullptr, nullptr);
    {
        dim3 grid((N + 127) / 128, HDIM / 256);
        gemm_f16<0><<<grid, 256, SMEM_TOT>>>(xh, ag1, w1h, b1, h1, nullptr, nullptr, N, FDIM);
    }

    // ---- layer 2 (head fused; gather also inits logits to bo) ----
    gather_f16<64><<<(N + 3) / 4, 256>>>(h1, off, eid, inv, ag2, N, bo, out);
    {
        dim3 grid((N + 127) / 128, HDIM / 256);
        gemm_f16<1><<<grid, 256, SMEM_TOT>>>(h1, ag2, w2h, b2, nullptr, Wo, out, N, HDIM);
    }

    sigmoid_kernel<<<(N + T - 1) / T, T>>>(out, N);
}

// round 11
// speedup vs baseline: 1.7045x; 1.7045x over previous
#include <cuda_runtime.h>
#include <cuda_fp16.h>
#include <cstdint>
#include <math.h>

// ---------------------------------------------------------------------------
// GraphSAGE fraud detector — round 10.
//  * CSR scan parallelized across SMs (2 small grid-wide kernels) — the old
//    grid=1 scan was ~100us of serial gmem latency (ncu rounds 8-9).
//  * GEMM config identical to the 420us round-7 run: 128x256 CTA, 64x64 warp
//    tile, 3-stage cp.async, wait_group 1.
// ---------------------------------------------------------------------------

#define MAXN 50048
#define MAXE 409600
#define HDIM 512
#define FDIM 128

#define STAGES   3
#define ASTAGE   8192     // 128 rows x 32 fp16
#define BSTAGE   16384    // 256 rows x 32 fp16
#define SMEM_TOT (STAGES * (ASTAGE + BSTAGE))   // 73728

#define SCANB    1024     // elements per scan block
#define NSCANB   ((MAXN + SCANB - 1) / SCANB)

__device__ __align__(16) float  g_inv[MAXN];
__device__ __align__(16) __half g_xh [(size_t)MAXN * FDIM];
__device__ __align__(16) __half g_ag1[(size_t)MAXN * FDIM];
__device__ __align__(16) __half g_h1 [(size_t)MAXN * HDIM];
__device__ __align__(16) __half g_ag2[(size_t)MAXN * HDIM];
__device__ __align__(16) __half g_w1h[(size_t)HDIM * 256];
__device__ __align__(16) __half g_w2h[(size_t)HDIM * 1024];
__device__ int g_cnt[MAXN];
__device__ int g_off[MAXN + 1];
__device__ int g_eid[MAXE];
__device__ int g_bsum[NSCANB];

// ======================= helpers =============================

__device__ __forceinline__ uint32_t smem_u32(const void* p) {
    uint32_t a;
    asm("{ .reg .u64 t; cvta.to.shared.u64 t, %1; cvt.u32.u64 %0, t; }"
        : "=r"(a) : "l"(p));
    return a;
}

__device__ __forceinline__ void ldsm4(uint32_t* r, uint32_t addr) {
    asm volatile("ldmatrix.sync.aligned.m8n8.x4.shared.b16 {%0,%1,%2,%3}, [%4];"
                 : "=r"(r[0]), "=r"(r[1]), "=r"(r[2]), "=r"(r[3]) : "r"(addr));
}

__device__ __forceinline__ void mma16816(float* d, const uint32_t* a, const uint32_t* b) {
    asm volatile(
        "mma.sync.aligned.m16n8k16.row.col.f32.f16.f16.f32 "
        "{%0,%1,%2,%3}, {%4,%5,%6,%7}, {%8,%9}, {%0,%1,%2,%3};"
        : "+f"(d[0]), "+f"(d[1]), "+f"(d[2]), "+f"(d[3])
        : "r"(a[0]), "r"(a[1]), "r"(a[2]), "r"(a[3]), "r"(b[0]), "r"(b[1]));
}

__device__ __forceinline__ void cp16(uint32_t dst, const void* src, int src_sz) {
    asm volatile("cp.async.cg.shared.global [%0], [%1], 16, %2;"
                 :: "r"(dst), "l"(src), "r"(src_sz) : "memory");
}

#define CP_COMMIT() asm volatile("cp.async.commit_group;" ::: "memory")
#define CP_WAIT1()  asm volatile("cp.async.wait_group 1;" ::: "memory")

__device__ __forceinline__ uint32_t pack_h2(float a, float b) {
    __half2 h = __floats2half2_rn(a, b);
    return *(uint32_t*)&h;
}

// 2 logical rows per 128B physical row, XOR swizzle over 8 16B slots.
__device__ __forceinline__ uint32_t taddr(int r, int c16) {
    return (uint32_t)((r >> 1) * 128 + ((((r & 1) * 4 + c16) ^ ((r >> 1) & 7)) << 4));
}

// ======================= CSR build =============================

__global__ void zeroi_kernel(int* __restrict__ p, int n) {
    int i = blockIdx.x * blockDim.x + threadIdx.x;
    if (i < n) p[i] = 0;
}

__global__ void count_kernel(const int* __restrict__ dst, int E, int* __restrict__ cnt) {
    int e = blockIdx.x * blockDim.x + threadIdx.x;
    if (e < E) atomicAdd(&cnt[dst[e]], 1);
}

// Pass 1: per-block local exclusive scan of a 1024-chunk of cnt.
// off[i] = local exclusive prefix; bsum[b] = block total.
// Also writes inv[i] = 1/max(c,1) and clears cnt for fill's counters.
__global__ void scan1_kernel(int* __restrict__ cnt, int* __restrict__ off,
                             float* __restrict__ inv, int* __restrict__ bsum, int n) {
    __shared__ int wsum[32];
    const int t    = threadIdx.x;
    const int lane = t & 31;
    const int wid  = t >> 5;
    const int i    = blockIdx.x * SCANB + t;

    int c = 0;
    if (i < n) {
        c = cnt[i];
        cnt[i] = 0;
        inv[i] = 1.0f / fmaxf((float)c, 1.0f);
    }
    int v = c;
#pragma unroll
    for (int o = 1; o < 32; o <<= 1) {
        int u = __shfl_up_sync(0xffffffffu, v, o);
        if (lane >= o) v += u;
    }
    if (lane == 31) wsum[wid] = v;
    __syncthreads();
    if (wid == 0) {
        int w = wsum[lane];
#pragma unroll
        for (int o = 1; o < 32; o <<= 1) {
            int u = __shfl_up_sync(0xffffffffu, w, o);
            if (lane >= o) w += u;
        }
        wsum[lane] = w;
    }
    __syncthreads();
    const int wexcl = (wid == 0) ? 0 : wsum[wid - 1];
    if (i < n) off[i] = wexcl + v - c;
    if (t == 1023) bsum[blockIdx.x] = wexcl + v;   // block total (inclusive)
}

// Pass 2: add exclusive prefix of bsum to each chunk; write off[n].
__global__ void scan2_kernel(int* __restrict__ off, const int* __restrict__ bsum,
                             int n, int nblocks) {
    __shared__ int spfx;
    const int t = threadIdx.x;
    const int b = blockIdx.x;
    if (t < 32) {
        int v = 0;
        for (int j = t; j < b; j += 32) v += bsum[j];   // <=2 iters for 49 blocks
#pragma unroll
        for (int o = 16; o; o >>= 1) v += __shfl_xor_sync(0xffffffffu, v, o);
        if (t == 0) spfx = v;
    }
    __syncthreads();
    const int i = b * SCANB + t;
    if (i < n) off[i] += spfx;
    if (b == gridDim.x - 1 && t == 1023) {
        int tot = 0;
        for (int j = 0; j < nblocks; ++j) tot += bsum[j];
        off[n] = tot;
    }
}

__global__ void fill_kernel(const int* __restrict__ src, const int* __restrict__ dst,
                            int E, const int* __restrict__ off,
                            int* __restrict__ pos, int* __restrict__ eid) {
    int e = blockIdx.x * blockDim.x + threadIdx.x;
    if (e < E) {
        int d = dst[e];
        int p = atomicAdd(&pos[d], 1);
        eid[off[d] + p] = src[e];
    }
}

// ---------------- fused fp32 -> fp16 convert: x, W1, W2 --------------------
__global__ void tohalf_all(const float* __restrict__ x,  __half* __restrict__ xh,  int nx4,
                           const float* __restrict__ w1, __half* __restrict__ w1h, int nw14,
                           const float* __restrict__ w2, __half* __restrict__ w2h, int nw24) {
    int i = blockIdx.x * blockDim.x + threadIdx.x;
    const float* sp; __half* dp;
    if (i < nx4)                { sp = x;  dp = xh; }
    else if (i < nx4 + nw14)    { sp = w1; dp = w1h; i -= nx4; }
    else if (i < nx4 + nw14 + nw24) { sp = w2; dp = w2h; i -= nx4 + nw14; }
    else return;
    float4 v = ((const float4*)sp)[i];
    uint2 o;
    o.x = pack_h2(v.x, v.y);
    o.y = pack_h2(v.z, v.w);
    ((uint2*)dp)[i] = o;
}

// ---------------- CSR gather (fp16): mean of incoming features -------------
template <int U>
__global__ void gather_f16(const __half* __restrict__ feat,
                           const int* __restrict__ off,
                           const int* __restrict__ eid,
                           const float* __restrict__ inv,
                           __half* __restrict__ outp, int N,
                           const float* __restrict__ bo, float* __restrict__ outInit) {
    const int g = blockIdx.x * (256 / U) + threadIdx.x / U;
    const int c = threadIdx.x % U;
    if (g >= N) return;
    if (bo != nullptr && c == 0) outInit[g] = bo[0];
    const int b  = off[g];
    const int e2 = off[g + 1];
    float acc[8];
#pragma unroll
    for (int q = 0; q < 8; ++q) acc[q] = 0.f;
    const uint4* base = (const uint4*)feat;
#pragma unroll 4
    for (int j = b; j < e2; ++j) {
        int s = __ldg(&eid[j]);
        uint4 u = __ldg(&base[(long long)s * U + c]);
        const __half2* h = (const __half2*)&u;
#pragma unroll
        for (int q = 0; q < 4; ++q) {
            float2 f = __half22float2(h[q]);
            acc[2 * q]     += f.x;
            acc[2 * q + 1] += f.y;
        }
    }
    const float sc = inv[g];
    uint4 o;
    o.x = pack_h2(acc[0] * sc, acc[1] * sc);
    o.y = pack_h2(acc[2] * sc, acc[3] * sc);
    o.z = pack_h2(acc[4] * sc, acc[5] * sc);
    o.w = pack_h2(acc[6] * sc, acc[7] * sc);
    ((uint4*)outp)[(long long)g * U + c] = o;
}

// =================== mma.sync fp16 concat-GEMM, 3-stage ====================
// CTA 128(M) x 256(N); 8 warps, each 64x64; K chunks of 32.
// FUSED 0: epilogue bias+ReLU -> fp16 C.
// FUSED 1: epilogue head: atomicAdd(outLogit[m], sum_n relu(.)*Wo[n]).

template <int FUSED>
__global__ void __launch_bounds__(256, 1)
gemm_f16(const __half* __restrict__ A1, const __half* __restrict__ A2,
         const __half* __restrict__ W,
         const float* __restrict__ bias, __half* __restrict__ C,
         const float* __restrict__ Wo, float* __restrict__ outLogit,
         int M, int Kh) {
    extern __shared__ __align__(128) uint8_t dynsmem[];
    const uint32_t sbA = smem_u32(dynsmem);
    const uint32_t sbB = sbA + STAGES * ASTAGE;

    const int tid  = threadIdx.x;
    const int wid  = tid >> 5;
    const int lane = tid & 31;
    const int wm   = wid & 1;
    const int wn   = wid >> 1;
    const int K    = 2 * Kh;
    const int m0   = blockIdx.x * 128;
    const int n0   = blockIdx.y * 256;

    const int qrow = lane & 15;
    const int qsel = lane >> 4;

    float acc[4][8][4];
#pragma unroll
    for (int i = 0; i < 4; ++i)
#pragma unroll
        for (int j = 0; j < 8; ++j)
#pragma unroll
            for (int r = 0; r < 4; ++r) acc[i][j][r] = 0.0f;

    const int nch = K >> 5;

    auto issue_chunk = [&](int ch, int st) {
        const int k0 = ch << 5;
        const bool useA2 = (k0 >= Kh);
        const int koff = useA2 ? k0 - Kh : k0;
        const __half* Ab = useA2 ? A2 : A1;
        const uint32_t abase = sbA + st * ASTAGE;
        const uint32_t bbase = sbB + st * BSTAGE;
#pragma unroll
        for (int u0 = 0; u0 < 2; ++u0) {
            const int u = tid + u0 * 256;
            const int row = u >> 2, c16 = u & 3;
            const int m = m0 + row;
            const void* src = Ab + (long long)m * Kh + koff + c16 * 8;
            cp16(abase + taddr(row, c16), src, (m < M) ? 16 : 0);
        }
#pragma unroll
        for (int u0 = 0; u0 < 4; ++u0) {
            const int u = tid + u0 * 256;
            const int row = u >> 2, c16 = u & 3;
            const void* src = W + (long long)(n0 + row) * K + k0 + c16 * 8;
            cp16(bbase + taddr(row, c16), src, 16);
        }
    };

    issue_chunk(0, 0); CP_COMMIT();
    issue_chunk(1, 1); CP_COMMIT();

    for (int ch = 0; ch < nch; ++ch) {
        CP_WAIT1();
        __syncthreads();
        {
            const int nxt = ch + STAGES - 1;
            if (nxt < nch) issue_chunk(nxt, nxt % STAGES);
            CP_COMMIT();
        }

        const int st = ch % STAGES;
        const uint32_t aST = sbA + st * ASTAGE;
        const uint32_t bST = sbB + st * BSTAGE;

#pragma unroll
        for (int s = 0; s < 2; ++s) {
            const int cc = s * 2 + qsel;
            uint32_t ah[4][4], bh[4][4];
#pragma unroll
            for (int i = 0; i < 4; ++i)
                ldsm4(ah[i], aST + taddr(wm * 64 + i * 16 + qrow, cc));
#pragma unroll
            for (int p = 0; p < 4; ++p)
                ldsm4(bh[p], bST + taddr(wn * 64 + p * 16 + qrow, cc));
#pragma unroll
            for (int i = 0; i < 4; ++i) {
#pragma unroll
                for (int p = 0; p < 4; ++p) {
                    uint32_t f0[2] = { bh[p][0], bh[p][2] };
                    uint32_t f1[2] = { bh[p][1], bh[p][3] };
                    mma16816(acc[i][2 * p],     ah[i], f0);
                    mma16816(acc[i][2 * p + 1], ah[i], f1);
                }
            }
        }
    }
    __syncthreads();

    if (FUSED == 0) {
#pragma unroll
        for (int j = 0; j < 8; ++j) {
            const int nb = n0 + wn * 64 + j * 8 + (lane & 3) * 2;
            const float b0f = bias[nb], b1f = bias[nb + 1];
#pragma unroll
            for (int i = 0; i < 4; ++i) {
                const int r0 = m0 + wm * 64 + i * 16 + (lane >> 2);
                if (r0 < M) {
                    *(uint32_t*)(C + (long long)r0 * HDIM + nb) =
                        pack_h2(fmaxf(acc[i][j][0] + b0f, 0.f),
                                fmaxf(acc[i][j][1] + b1f, 0.f));
                }
                const int r1 = r0 + 8;
                if (r1 < M) {
                    *(uint32_t*)(C + (long long)r1 * HDIM + nb) =
                        pack_h2(fmaxf(acc[i][j][2] + b0f, 0.f),
                                fmaxf(acc[i][j][3] + b1f, 0.f));
                }
            }
        }
    } else {
#pragma unroll
        for (int i = 0; i < 4; ++i) {
            float p0 = 0.f, p1 = 0.f;
#pragma unroll
            for (int j = 0; j < 8; ++j) {
                const int nb = n0 + wn * 64 + j * 8 + (lane & 3) * 2;
                const float b0f = bias[nb],  b1f = bias[nb + 1];
                const float w0 = __ldg(&Wo[nb]), w1 = __ldg(&Wo[nb + 1]);
                p0 += fmaxf(acc[i][j][0] + b0f, 0.f) * w0
                    + fmaxf(acc[i][j][1] + b1f, 0.f) * w1;
                p1 += fmaxf(acc[i][j][2] + b0f, 0.f) * w0
                    + fmaxf(acc[i][j][3] + b1f, 0.f) * w1;
            }
            p0 += __shfl_xor_sync(0xffffffffu, p0, 1);
            p0 += __shfl_xor_sync(0xffffffffu, p0, 2);
            p1 += __shfl_xor_sync(0xffffffffu, p1, 1);
            p1 += __shfl_xor_sync(0xffffffffu, p1, 2);
            if ((lane & 3) == 0) {
                const int r0 = m0 + wm * 64 + i * 16 + (lane >> 2);
                const int r1 = r0 + 8;
                if (r0 < M) atomicAdd(&outLogit[r0], p0);
                if (r1 < M) atomicAdd(&outLogit[r1], p1);
            }
        }
    }
}

// ---------------- sigmoid ----------------
__global__ void sigmoid_kernel(float* __restrict__ out, int n) {
    int i = blockIdx.x * blockDim.x + threadIdx.x;
    if (i < n) out[i] = 1.0f / (1.0f + expf(-out[i]));
}

// ---------------- launch ----------------

extern "C" void kernel_launch(void* const* d_in, const int* in_sizes, int n_in,
                              void* d_out, int out_size) {
    const float* x  = (const float*)d_in[0];
    const int*   ei = (const int*)  d_in[1];
    const float* W1 = (const float*)d_in[2];
    const float* b1 = (const float*)d_in[3];
    const float* W2 = (const float*)d_in[4];
    const float* b2 = (const float*)d_in[5];
    const float* Wo = (const float*)d_in[6];
    const float* bo = (const float*)d_in[7];
    float* out = (float*)d_out;

    const int N = in_sizes[0] / FDIM;
    const int E = in_sizes[1] / 2;
    const int* src = ei;
    const int* dst = ei + E;

    float *inv;
    __half *xh, *ag1, *h1, *ag2, *w1h, *w2h;
    int *cnt, *off, *eid, *bsum;
    cudaGetSymbolAddress((void**)&inv, g_inv);
    cudaGetSymbolAddress((void**)&xh,  g_xh);
    cudaGetSymbolAddress((void**)&ag1, g_ag1);
    cudaGetSymbolAddress((void**)&h1,  g_h1);
    cudaGetSymbolAddress((void**)&ag2, g_ag2);
    cudaGetSymbolAddress((void**)&w1h, g_w1h);
    cudaGetSymbolAddress((void**)&w2h, g_w2h);
    cudaGetSymbolAddress((void**)&cnt, g_cnt);
    cudaGetSymbolAddress((void**)&off, g_off);
    cudaGetSymbolAddress((void**)&eid, g_eid);
    cudaGetSymbolAddress((void**)&bsum, g_bsum);

    cudaFuncSetAttribute(gemm_f16<0>, cudaFuncAttributeMaxDynamicSharedMemorySize, SMEM_TOT);
    cudaFuncSetAttribute(gemm_f16<1>, cudaFuncAttributeMaxDynamicSharedMemorySize, SMEM_TOT);

    const int T = 256;
    const int nscan = (N + SCANB - 1) / SCANB;

    // ---- converts (no CSR dependency) ----
    const int nx4  = N * FDIM / 4;
    const int nw14 = HDIM * 2 * FDIM / 4;
    const int nw24 = HDIM * 2 * HDIM / 4;
    const int tot4 = nx4 + nw14 + nw24;
    tohalf_all<<<(tot4 + T - 1) / T, T>>>(x, xh, nx4, W1, w1h, nw14, W2, w2h, nw24);

    // ---- CSR build (scan parallel across SMs) ----
    zeroi_kernel<<<(N + T - 1) / T, T>>>(cnt, N);
    count_kernel<<<(E + T - 1) / T, T>>>(dst, E, cnt);
    scan1_kernel<<<nscan, SCANB>>>(cnt, off, inv, bsum, N);
    scan2_kernel<<<nscan, SCANB>>>(off, bsum, N, nscan);
    fill_kernel<<<(E + T - 1) / T, T>>>(src, dst, E, off, cnt, eid);

    // ---- layer 1 ----
    gather_f16<16><<<(N + 15) / 16, 256>>>(xh, off, eid, inv, ag1, N, nullptr, nullptr);
    {
        dim3 grid((N + 127) / 128, HDIM / 256);
        gemm_f16<0><<<grid, 256, SMEM_TOT>>>(xh, ag1, w1h, b1, h1, nullptr, nullptr, N, FDIM);
    }

    // ---- layer 2 (head fused; gather also inits logits to bo) ----
    gather_f16<64><<<(N + 3) / 4, 256>>>(h1, off, eid, inv, ag2, N, bo, out);
    {
        dim3 grid((N + 127) / 128, HDIM / 256);
        gemm_f16<1><<<grid, 256, SMEM_TOT>>>(h1, ag2, w2h, b2, nullptr, Wo, out, N, HDIM);
    }

    sigmoid_kernel<<<(N + T - 1) / T, T>>>(out, N);
}

// round 12
// speedup vs baseline: 1.8999x; 1.1147x over previous
#include <cuda_runtime.h>
#include <cuda_fp16.h>
#include <cstdint>
#include <math.h>

// ---------------------------------------------------------------------------
// GraphSAGE fraud detector — round 11.
//  * GEMM: CTA 128x128, warp 64x32, 3-stage cp.async, 2 CTAs/SM (latency
//    hiding across co-resident CTAs; finer wave quantum).
//  * cnt-clear folded into the convert kernel (one fewer serial launch).
//  * Parallel CSR scan; head fused into GEMM2 epilogue.
// ---------------------------------------------------------------------------

#define MAXN 50048
#define MAXE 409600
#define HDIM 512
#define FDIM 128

#define STAGES   3
#define ASTAGE   8192     // 128 rows x 32 fp16
#define BSTAGE   8192     // 128 rows x 32 fp16
#define SMEM_TOT (STAGES * (ASTAGE + BSTAGE))   // 49152

#define SCANB    1024
#define NSCANB   ((MAXN + SCANB - 1) / SCANB)

__device__ __align__(16) float  g_inv[MAXN];
__device__ __align__(16) __half g_xh [(size_t)MAXN * FDIM];
__device__ __align__(16) __half g_ag1[(size_t)MAXN * FDIM];
__device__ __align__(16) __half g_h1 [(size_t)MAXN * HDIM];
__device__ __align__(16) __half g_ag2[(size_t)MAXN * HDIM];
__device__ __align__(16) __half g_w1h[(size_t)HDIM * 256];
__device__ __align__(16) __half g_w2h[(size_t)HDIM * 1024];
__device__ int g_cnt[MAXN];
__device__ int g_off[MAXN + 1];
__device__ int g_eid[MAXE];
__device__ int g_bsum[NSCANB];

// ======================= helpers =============================

__device__ __forceinline__ uint32_t smem_u32(const void* p) {
    uint32_t a;
    asm("{ .reg .u64 t; cvta.to.shared.u64 t, %1; cvt.u32.u64 %0, t; }"
        : "=r"(a) : "l"(p));
    return a;
}

__device__ __forceinline__ void ldsm4(uint32_t* r, uint32_t addr) {
    asm volatile("ldmatrix.sync.aligned.m8n8.x4.shared.b16 {%0,%1,%2,%3}, [%4];"
                 : "=r"(r[0]), "=r"(r[1]), "=r"(r[2]), "=r"(r[3]) : "r"(addr));
}

__device__ __forceinline__ void mma16816(float* d, const uint32_t* a, const uint32_t* b) {
    asm volatile(
        "mma.sync.aligned.m16n8k16.row.col.f32.f16.f16.f32 "
        "{%0,%1,%2,%3}, {%4,%5,%6,%7}, {%8,%9}, {%0,%1,%2,%3};"
        : "+f"(d[0]), "+f"(d[1]), "+f"(d[2]), "+f"(d[3])
        : "r"(a[0]), "r"(a[1]), "r"(a[2]), "r"(a[3]), "r"(b[0]), "r"(b[1]));
}

__device__ __forceinline__ void cp16(uint32_t dst, const void* src, int src_sz) {
    asm volatile("cp.async.cg.shared.global [%0], [%1], 16, %2;"
                 :: "r"(dst), "l"(src), "r"(src_sz) : "memory");
}

#define CP_COMMIT() asm volatile("cp.async.commit_group;" ::: "memory")
#define CP_WAIT1()  asm volatile("cp.async.wait_group 1;" ::: "memory")

__device__ __forceinline__ uint32_t pack_h2(float a, float b) {
    __half2 h = __floats2half2_rn(a, b);
    return *(uint32_t*)&h;
}

// 2 logical rows per 128B physical row, XOR swizzle over 8 16B slots.
__device__ __forceinline__ uint32_t taddr(int r, int c16) {
    return (uint32_t)((r >> 1) * 128 + ((((r & 1) * 4 + c16) ^ ((r >> 1) & 7)) << 4));
}

// ======================= fused convert + cnt clear =========================

__global__ void tohalf_all(const float* __restrict__ x,  __half* __restrict__ xh,  int nx4,
                           const float* __restrict__ w1, __half* __restrict__ w1h, int nw14,
                           const float* __restrict__ w2, __half* __restrict__ w2h, int nw24,
                           int* __restrict__ cnt, int ncnt) {
    int i = blockIdx.x * blockDim.x + threadIdx.x;
    const int tot = nx4 + nw14 + nw24;
    if (i < tot) {
        const float* sp; __half* dp;
        if (i < nx4)             { sp = x;  dp = xh; }
        else if (i < nx4 + nw14) { sp = w1; dp = w1h; i -= nx4; }
        else                     { sp = w2; dp = w2h; i -= nx4 + nw14; }
        float4 v = ((const float4*)sp)[i];
        uint2 o;
        o.x = pack_h2(v.x, v.y);
        o.y = pack_h2(v.z, v.w);
        ((uint2*)dp)[i] = o;
    } else {
        int j = i - tot;
        if (j < ncnt) cnt[j] = 0;
    }
}

// ======================= CSR build =============================

__global__ void count_kernel(const int* __restrict__ dst, int E, int* __restrict__ cnt) {
    int e = blockIdx.x * blockDim.x + threadIdx.x;
    if (e < E) atomicAdd(&cnt[dst[e]], 1);
}

__global__ void scan1_kernel(int* __restrict__ cnt, int* __restrict__ off,
                             float* __restrict__ inv, int* __restrict__ bsum, int n) {
    __shared__ int wsum[32];
    const int t    = threadIdx.x;
    const int lane = t & 31;
    const int wid  = t >> 5;
    const int i    = blockIdx.x * SCANB + t;

    int c = 0;
    if (i < n) {
        c = cnt[i];
        cnt[i] = 0;
        inv[i] = 1.0f / fmaxf((float)c, 1.0f);
    }
    int v = c;
#pragma unroll
    for (int o = 1; o < 32; o <<= 1) {
        int u = __shfl_up_sync(0xffffffffu, v, o);
        if (lane >= o) v += u;
    }
    if (lane == 31) wsum[wid] = v;
    __syncthreads();
    if (wid == 0) {
        int w = wsum[lane];
#pragma unroll
        for (int o = 1; o < 32; o <<= 1) {
            int u = __shfl_up_sync(0xffffffffu, w, o);
            if (lane >= o) w += u;
        }
        wsum[lane] = w;
    }
    __syncthreads();
    const int wexcl = (wid == 0) ? 0 : wsum[wid - 1];
    if (i < n) off[i] = wexcl + v - c;
    if (t == 1023) bsum[blockIdx.x] = wexcl + v;
}

__global__ void scan2_kernel(int* __restrict__ off, const int* __restrict__ bsum,
                             int n, int nblocks) {
    __shared__ int spfx;
    const int t = threadIdx.x;
    const int b = blockIdx.x;
    if (t < 32) {
        int v = 0;
        for (int j = t; j < b; j += 32) v += bsum[j];
#pragma unroll
        for (int o = 16; o; o >>= 1) v += __shfl_xor_sync(0xffffffffu, v, o);
        if (t == 0) spfx = v;
    }
    __syncthreads();
    const int i = b * SCANB + t;
    if (i < n) off[i] += spfx;
    if (b == gridDim.x - 1 && t == 1023) {
        int tot = 0;
        for (int j = 0; j < nblocks; ++j) tot += bsum[j];
        off[n] = tot;
    }
}

__global__ void fill_kernel(const int* __restrict__ src, const int* __restrict__ dst,
                            int E, const int* __restrict__ off,
                            int* __restrict__ pos, int* __restrict__ eid) {
    int e = blockIdx.x * blockDim.x + threadIdx.x;
    if (e < E) {
        int d = dst[e];
        int p = atomicAdd(&pos[d], 1);
        eid[off[d] + p] = src[e];
    }
}

// ---------------- CSR gather (fp16): mean of incoming features -------------
template <int U>
__global__ void gather_f16(const __half* __restrict__ feat,
                           const int* __restrict__ off,
                           const int* __restrict__ eid,
                           const float* __restrict__ inv,
                           __half* __restrict__ outp, int N,
                           const float* __restrict__ bo, float* __restrict__ outInit) {
    const int g = blockIdx.x * (256 / U) + threadIdx.x / U;
    const int c = threadIdx.x % U;
    if (g >= N) return;
    if (bo != nullptr && c == 0) outInit[g] = bo[0];
    const int b  = off[g];
    const int e2 = off[g + 1];
    float acc[8];
#pragma unroll
    for (int q = 0; q < 8; ++q) acc[q] = 0.f;
    const uint4* base = (const uint4*)feat;
#pragma unroll 4
    for (int j = b; j < e2; ++j) {
        int s = __ldg(&eid[j]);
        uint4 u = __ldg(&base[(long long)s * U + c]);
        const __half2* h = (const __half2*)&u;
#pragma unroll
        for (int q = 0; q < 4; ++q) {
            float2 f = __half22float2(h[q]);
            acc[2 * q]     += f.x;
            acc[2 * q + 1] += f.y;
        }
    }
    const float sc = inv[g];
    uint4 o;
    o.x = pack_h2(acc[0] * sc, acc[1] * sc);
    o.y = pack_h2(acc[2] * sc, acc[3] * sc);
    o.z = pack_h2(acc[4] * sc, acc[5] * sc);
    o.w = pack_h2(acc[6] * sc, acc[7] * sc);
    ((uint4*)outp)[(long long)g * U + c] = o;
}

// =================== mma.sync fp16 concat-GEMM, 3-stage, 2 CTA/SM ==========
// CTA 128(M) x 128(N); 8 warps, each 64x32; K chunks of 32.
// FUSED 0: epilogue bias+ReLU -> fp16 C.
// FUSED 1: epilogue head: atomicAdd(outLogit[m], sum_n relu(.)*Wo[n]).

template <int FUSED>
__global__ void __launch_bounds__(256, 2)
gemm_f16(const __half* __restrict__ A1, const __half* __restrict__ A2,
         const __half* __restrict__ W,
         const float* __restrict__ bias, __half* __restrict__ C,
         const float* __restrict__ Wo, float* __restrict__ outLogit,
         int M, int Kh) {
    extern __shared__ __align__(128) uint8_t dynsmem[];
    const uint32_t sbA = smem_u32(dynsmem);
    const uint32_t sbB = sbA + STAGES * ASTAGE;

    const int tid  = threadIdx.x;
    const int wid  = tid >> 5;
    const int lane = tid & 31;
    const int wm   = wid & 1;        // 64-row band
    const int wn   = wid >> 1;       // 32-col band (0..3)
    const int K    = 2 * Kh;
    const int m0   = blockIdx.x * 128;
    const int n0   = blockIdx.y * 128;

    const int qrow = lane & 15;
    const int qsel = lane >> 4;

    float acc[4][4][4];
#pragma unroll
    for (int i = 0; i < 4; ++i)
#pragma unroll
        for (int j = 0; j < 4; ++j)
#pragma unroll
            for (int r = 0; r < 4; ++r) acc[i][j][r] = 0.0f;

    const int nch = K >> 5;

    auto issue_chunk = [&](int ch, int st) {
        const int k0 = ch << 5;
        const bool useA2 = (k0 >= Kh);
        const int koff = useA2 ? k0 - Kh : k0;
        const __half* Ab = useA2 ? A2 : A1;
        const uint32_t abase = sbA + st * ASTAGE;
        const uint32_t bbase = sbB + st * BSTAGE;
        // A: 512 16B units, 2 per thread
#pragma unroll
        for (int u0 = 0; u0 < 2; ++u0) {
            const int u = tid + u0 * 256;
            const int row = u >> 2, c16 = u & 3;
            const int m = m0 + row;
            const void* src = Ab + (long long)m * Kh + koff + c16 * 8;
            cp16(abase + taddr(row, c16), src, (m < M) ? 16 : 0);
        }
        // B: 512 16B units, 2 per thread (rows always valid)
#pragma unroll
        for (int u0 = 0; u0 < 2; ++u0) {
            const int u = tid + u0 * 256;
            const int row = u >> 2, c16 = u & 3;
            const void* src = W + (long long)(n0 + row) * K + k0 + c16 * 8;
            cp16(bbase + taddr(row, c16), src, 16);
        }
    };

    issue_chunk(0, 0); CP_COMMIT();
    issue_chunk(1, 1); CP_COMMIT();

    for (int ch = 0; ch < nch; ++ch) {
        CP_WAIT1();
        __syncthreads();
        {
            const int nxt = ch + STAGES - 1;
            if (nxt < nch) issue_chunk(nxt, nxt % STAGES);
            CP_COMMIT();
        }

        const int st = ch % STAGES;
        const uint32_t aST = sbA + st * ASTAGE;
        const uint32_t bST = sbB + st * BSTAGE;

#pragma unroll
        for (int s = 0; s < 2; ++s) {
            const int cc = s * 2 + qsel;
            uint32_t ah[4][4], bh[2][4];
#pragma unroll
            for (int i = 0; i < 4; ++i)
                ldsm4(ah[i], aST + taddr(wm * 64 + i * 16 + qrow, cc));
#pragma unroll
            for (int p = 0; p < 2; ++p)
                ldsm4(bh[p], bST + taddr(wn * 32 + p * 16 + qrow, cc));
#pragma unroll
            for (int i = 0; i < 4; ++i) {
#pragma unroll
                for (int p = 0; p < 2; ++p) {
                    uint32_t f0[2] = { bh[p][0], bh[p][2] };
                    uint32_t f1[2] = { bh[p][1], bh[p][3] };
                    mma16816(acc[i][2 * p],     ah[i], f0);
                    mma16816(acc[i][2 * p + 1], ah[i], f1);
                }
            }
        }
    }
    __syncthreads();

    if (FUSED == 0) {
#pragma unroll
        for (int j = 0; j < 4; ++j) {
            const int nb = n0 + wn * 32 + j * 8 + (lane & 3) * 2;
            const float b0f = bias[nb], b1f = bias[nb + 1];
#pragma unroll
            for (int i = 0; i < 4; ++i) {
                const int r0 = m0 + wm * 64 + i * 16 + (lane >> 2);
                if (r0 < M) {
                    *(uint32_t*)(C + (long long)r0 * HDIM + nb) =
                        pack_h2(fmaxf(acc[i][j][0] + b0f, 0.f),
                                fmaxf(acc[i][j][1] + b1f, 0.f));
                }
                const int r1 = r0 + 8;
                if (r1 < M) {
                    *(uint32_t*)(C + (long long)r1 * HDIM + nb) =
                        pack_h2(fmaxf(acc[i][j][2] + b0f, 0.f),
                                fmaxf(acc[i][j][3] + b1f, 0.f));
                }
            }
        }
    } else {
#pragma unroll
        for (int i = 0; i < 4; ++i) {
            float p0 = 0.f, p1 = 0.f;
#pragma unroll
            for (int j = 0; j < 4; ++j) {
                const int nb = n0 + wn * 32 + j * 8 + (lane & 3) * 2;
                const float b0f = bias[nb],  b1f = bias[nb + 1];
                const float w0 = __ldg(&Wo[nb]), w1 = __ldg(&Wo[nb + 1]);
                p0 += fmaxf(acc[i][j][0] + b0f, 0.f) * w0
                    + fmaxf(acc[i][j][1] + b1f, 0.f) * w1;
                p1 += fmaxf(acc[i][j][2] + b0f, 0.f) * w0
                    + fmaxf(acc[i][j][3] + b1f, 0.f) * w1;
            }
            p0 += __shfl_xor_sync(0xffffffffu, p0, 1);
            p0 += __shfl_xor_sync(0xffffffffu, p0, 2);
            p1 += __shfl_xor_sync(0xffffffffu, p1, 1);
            p1 += __shfl_xor_sync(0xffffffffu, p1, 2);
            if ((lane & 3) == 0) {
                const int r0 = m0 + wm * 64 + i * 16 + (lane >> 2);
                const int r1 = r0 + 8;
                if (r0 < M) atomicAdd(&outLogit[r0], p0);
                if (r1 < M) atomicAdd(&outLogit[r1], p1);
            }
        }
    }
}

// ---------------- sigmoid ----------------
__global__ void sigmoid_kernel(float* __restrict__ out, int n) {
    int i = blockIdx.x * blockDim.x + threadIdx.x;
    if (i < n) out[i] = 1.0f / (1.0f + expf(-out[i]));
}

// ---------------- launch ----------------

extern "C" void kernel_launch(void* const* d_in, const int* in_sizes, int n_in,
                              void* d_out, int out_size) {
    const float* x  = (const float*)d_in[0];
    const int*   ei = (const int*)  d_in[1];
    const float* W1 = (const float*)d_in[2];
    const float* b1 = (const float*)d_in[3];
    const float* W2 = (const float*)d_in[4];
    const float* b2 = (const float*)d_in[5];
    const float* Wo = (const float*)d_in[6];
    const float* bo = (const float*)d_in[7];
    float* out = (float*)d_out;

    const int N = in_sizes[0] / FDIM;
    const int E = in_sizes[1] / 2;
    const int* src = ei;
    const int* dst = ei + E;

    float *inv;
    __half *xh, *ag1, *h1, *ag2, *w1h, *w2h;
    int *cnt, *off, *eid, *bsum;
    cudaGetSymbolAddress((void**)&inv, g_inv);
    cudaGetSymbolAddress((void**)&xh,  g_xh);
    cudaGetSymbolAddress((void**)&ag1, g_ag1);
    cudaGetSymbolAddress((void**)&h1,  g_h1);
    cudaGetSymbolAddress((void**)&ag2, g_ag2);
    cudaGetSymbolAddress((void**)&w1h, g_w1h);
    cudaGetSymbolAddress((void**)&w2h, g_w2h);
    cudaGetSymbolAddress((void**)&cnt, g_cnt);
    cudaGetSymbolAddress((void**)&off, g_off);
    cudaGetSymbolAddress((void**)&eid, g_eid);
    cudaGetSymbolAddress((void**)&bsum, g_bsum);

    cudaFuncSetAttribute(gemm_f16<0>, cudaFuncAttributeMaxDynamicSharedMemorySize, SMEM_TOT);
    cudaFuncSetAttribute(gemm_f16<1>, cudaFuncAttributeMaxDynamicSharedMemorySize, SMEM_TOT);

    const int T = 256;
    const int nscan = (N + SCANB - 1) / SCANB;

    // ---- converts + cnt clear (one kernel, no serial hop) ----
    const int nx4  = N * FDIM / 4;
    const int nw14 = HDIM * 2 * FDIM / 4;
    const int nw24 = HDIM * 2 * HDIM / 4;
    const int tot  = nx4 + nw14 + nw24 + N;
    tohalf_all<<<(tot + T - 1) / T, T>>>(x, xh, nx4, W1, w1h, nw14, W2, w2h, nw24, cnt, N);

    // ---- CSR build ----
    count_kernel<<<(E + T - 1) / T, T>>>(dst, E, cnt);
    scan1_kernel<<<nscan, SCANB>>>(cnt, off, inv, bsum, N);
    scan2_kernel<<<nscan, SCANB>>>(off, bsum, N, nscan);
    fill_kernel<<<(E + T - 1) / T, T>>>(src, dst, E, off, cnt, eid);

    // ---- layer 1 ----
    gather_f16<16><<<(N + 15) / 16, 256>>>(xh, off, eid, inv, ag1, N, nullptr, nullptr);
    {
        dim3 grid((N + 127) / 128, HDIM / 128);
        gemm_f16<0><<<grid, 256, SMEM_TOT>>>(xh, ag1, w1h, b1, h1, nullptr, nullptr, N, FDIM);
    }

    // ---- layer 2 (head fused; gather also inits logits to bo) ----
    gather_f16<64><<<(N + 3) / 4, 256>>>(h1, off, eid, inv, ag2, N, bo, out);
    {
        dim3 grid((N + 127) / 128, HDIM / 128);
        gemm_f16<1><<<grid, 256, SMEM_TOT>>>(h1, ag2, w2h, b2, nullptr, Wo, out, N, HDIM);
    }

    sigmoid_kernel<<<(N + T - 1) / T, T>>>(out, N);
}